// round 16
// baseline (speedup 1.0000x reference)
#include <cuda_runtime.h>
#include <cuda_bf16.h>
#include <math.h>

#define N_NODES 50000
#define D_MODEL 128
#define H_HEADS 8
#define DH 16
#define DFF 512
#define E_EDGES 800000
#define LN_EPS 1e-6f
#define NEG_SLOPE 0.2f
#define SCAN_B 196           // 196*256 = 50176 >= N_NODES+1
#define PREP_B 144           // kprep weight blocks
#define K1_B   782           // blocks: ceil(50000/64)

// ---------------- scratch (no allocations allowed) ----------------
__device__ __align__(16) float g_x[(size_t)N_NODES * D_MODEL];   // projected features [N,128]
__device__ __align__(16) float g_as[N_NODES * H_HEADS];          // alpha_src logits
__device__ __align__(16) float g_ad[N_NODES * H_HEADS];          // alpha_dst logits
// CSR-by-dst build
__device__ __align__(16) unsigned g_cnt[SCAN_B * 256];
__device__ __align__(16) unsigned g_off[N_NODES + 1];
__device__ __align__(16) unsigned g_cur[N_NODES];
__device__ __align__(16) unsigned g_bsum[256];
__device__ __align__(16) int      g_srcs[E_EDGES];
// packed split-bf16 weights: uint4 = (hi[kh], hi[kh+4], lo[kh], lo[kh+4])
__device__ __align__(16) uint4 g_w1p[32 * DFF];                  // W1 (k=128 -> 32 khIdx)
__device__ __align__(16) uint4 g_w2p[128 * D_MODEL];             // W2 (k=512 -> 128 khIdx)
__device__ __align__(16) uint4 g_wAp[32 * D_MODEL];              // W_att

__device__ __forceinline__ float leaky(float x) { return x > 0.f ? x : NEG_SLOPE * x; }

__device__ __forceinline__ void split_pack(float x0, float x1, unsigned& hi, unsigned& lo) {
    __nv_bfloat162 h = __floats2bfloat162_rn(x0, x1);
    float2 hf = __bfloat1622float2(h);
    __nv_bfloat162 l = __floats2bfloat162_rn(x0 - hf.x, x1 - hf.y);
    hi = *reinterpret_cast<unsigned*>(&h);
    lo = *reinterpret_cast<unsigned*>(&l);
}

__device__ __forceinline__ void mma16816(float* c, const unsigned* a, unsigned b0, unsigned b1) {
    asm volatile(
        "mma.sync.aligned.m16n8k16.row.col.f32.bf16.bf16.f32 "
        "{%0,%1,%2,%3}, {%4,%5,%6,%7}, {%8,%9}, {%0,%1,%2,%3};"
        : "+f"(c[0]), "+f"(c[1]), "+f"(c[2]), "+f"(c[3])
        : "r"(a[0]), "r"(a[1]), "r"(a[2]), "r"(a[3]), "r"(b0), "r"(b1));
}

__device__ __forceinline__ void ldsm_x4(unsigned* r, unsigned addr) {
    asm volatile("ldmatrix.sync.aligned.m8n8.x4.shared.b16 {%0,%1,%2,%3}, [%4];"
        : "=r"(r[0]), "=r"(r[1]), "=r"(r[2]), "=r"(r[3]) : "r"(addr));
}

__device__ __forceinline__ unsigned smem_u32(const void* p) {
    return (unsigned)__cvta_generic_to_shared(p);
}

// ---------------- Kprep: weight split/pack + g_cnt zero (fused) ----
__global__ void __launch_bounds__(256) kprep(const float* __restrict__ W1,
                                             const float* __restrict__ W2,
                                             const float* __restrict__ WA) {
    if (blockIdx.x >= PREP_B) {              // zero g_cnt
        g_cnt[(blockIdx.x - PREP_B) * 256 + threadIdx.x] = 0u;
        return;
    }
    int i = blockIdx.x * 256 + threadIdx.x;
    const float* W; int cols, idx; uint4* dst;
    if (i < 32 * DFF)                       { W = W1; cols = DFF;     idx = i;                       dst = g_w1p; }
    else if (i < 32 * DFF + 128 * D_MODEL)  { W = W2; cols = D_MODEL; idx = i - 32 * DFF;            dst = g_w2p; }
    else                                    { W = WA; cols = D_MODEL; idx = i - 32 * DFF - 128 * D_MODEL; dst = g_wAp; }
    int khi = idx / cols, n = idx % cols;
    int ks = khi >> 2, q = khi & 3;
    int kh = ks * 8 + q;
    unsigned h0, l0, h1, l1;
    split_pack(W[(2 * kh) * cols + n],     W[(2 * kh + 1) * cols + n], h0, l0);
    split_pack(W[(2 * kh + 8) * cols + n], W[(2 * kh + 9) * cols + n], h1, l1);
    dst[idx] = make_uint4(h0, h1, l0, l1);
}

// ---------------- CSR build -----------------------------------------
__global__ void __launch_bounds__(256) ks_hist(const int* __restrict__ ei) {
    int e = blockIdx.x * 256 + threadIdx.x;
    if (e < E_EDGES) atomicAdd(&g_cnt[__ldg(ei + E_EDGES + e)], 1u);
}
__global__ void __launch_bounds__(256) ks_scan1() {
    __shared__ unsigned s[256];
    int t = threadIdx.x;
    s[t] = g_cnt[blockIdx.x * 256 + t];
    __syncthreads();
#pragma unroll
    for (int o = 128; o; o >>= 1) {
        if (t < o) s[t] += s[t + o];
        __syncthreads();
    }
    if (t == 0) g_bsum[blockIdx.x] = s[0];
}
__global__ void __launch_bounds__(256) ks_scan3() {
    __shared__ unsigned s[256];
    __shared__ unsigned boff_s;
    int t = threadIdx.x;
    {
        unsigned v = (t < blockIdx.x && t < SCAN_B) ? g_bsum[t] : 0u;
        s[t] = v;
        __syncthreads();
#pragma unroll
        for (int o = 128; o; o >>= 1) {
            if (t < o) s[t] += s[t + o];
            __syncthreads();
        }
        if (t == 0) boff_s = s[0];
        __syncthreads();
    }
    int i = blockIdx.x * 256 + t;
    unsigned v = g_cnt[i];
    s[t] = v;
    __syncthreads();
#pragma unroll
    for (int o = 1; o < 256; o <<= 1) {
        unsigned add = (t >= o) ? s[t - o] : 0u;
        __syncthreads();
        s[t] += add;
        __syncthreads();
    }
    unsigned excl = s[t] - v + boff_s;
    if (i <= N_NODES) g_off[i] = excl;
    if (i < N_NODES)  g_cur[i] = excl;
}
__global__ void __launch_bounds__(256) ks_scat(const int* __restrict__ ei) {
    int e = blockIdx.x * 256 + threadIdx.x;
    if (e >= E_EDGES) return;
    int src = __ldg(ei + e), dst = __ldg(ei + E_EDGES + e);
    unsigned p = atomicAdd(&g_cur[dst], 1u);
    g_srcs[p] = src;
}

// ---------------- K1: LN1 -> x = h1 @ W_att (MMA); a_s, a_d; out=nf+bias
__global__ void __launch_bounds__(256) k1_ln_proj(const float* __restrict__ nf,
                                                  const float* __restrict__ g1,
                                                  const float* __restrict__ b1v,
                                                  const float* __restrict__ bias_att,
                                                  const float* __restrict__ asrc,
                                                  const float* __restrict__ adst,
                                                  float* __restrict__ out) {
    extern __shared__ unsigned sm[];
    unsigned* H1H = sm;
    unsigned* H1L = sm + 4352;
    float* XS = (float*)sm;              // aliases H1 after phase B

    const int t = threadIdx.x;
    const int lane = t & 31, w = t >> 5;
    const int g4 = lane >> 2, q4 = lane & 3;
    const int row0 = blockIdx.x * 64;
    const int valid = min(64, N_NODES - row0);

    {
        int r = t >> 2, q = t & 3;
        if (r < valid) {
            int grow = row0 + r;
            const float4* rp = (const float4*)(nf + (size_t)grow * D_MODEL + q * 32);
            float v[32];
#pragma unroll
            for (int j = 0; j < 8; j++) {
                float4 x = rp[j];
                v[4 * j] = x.x; v[4 * j + 1] = x.y; v[4 * j + 2] = x.z; v[4 * j + 3] = x.w;
            }
            float4* op = (float4*)(out + (size_t)grow * D_MODEL + q * 32);
#pragma unroll
            for (int j = 0; j < 8; j++) {
                int c = q * 32 + 4 * j;
                op[j] = make_float4(v[4 * j]     + __ldg(bias_att + c),
                                    v[4 * j + 1] + __ldg(bias_att + c + 1),
                                    v[4 * j + 2] + __ldg(bias_att + c + 2),
                                    v[4 * j + 3] + __ldg(bias_att + c + 3));
            }
            float s = 0.f, s2 = 0.f;
#pragma unroll
            for (int j = 0; j < 32; j++) { s += v[j]; s2 += v[j] * v[j]; }
            s  += __shfl_xor_sync(0xffffffffu, s, 1);
            s  += __shfl_xor_sync(0xffffffffu, s, 2);
            s2 += __shfl_xor_sync(0xffffffffu, s2, 1);
            s2 += __shfl_xor_sync(0xffffffffu, s2, 2);
            float mean = s * (1.f / 128.f);
            float var = (s2 * (1.f / 128.f) - mean * mean) * (128.f / 127.f);
            float rstd = 1.f / (sqrtf(fmaxf(var, 0.f)) + LN_EPS);
#pragma unroll
            for (int j = 0; j < 16; j++) {
                int c = q * 32 + 2 * j;
                float y0 = __ldg(g1 + c)     * (v[2 * j]     - mean) * rstd + __ldg(b1v + c);
                float y1 = __ldg(g1 + c + 1) * (v[2 * j + 1] - mean) * rstd + __ldg(b1v + c + 1);
                unsigned hi, lo;
                split_pack(y0, y1, hi, lo);
                H1H[r * 68 + q * 16 + j] = hi;
                H1L[r * 68 + q * 16 + j] = lo;
            }
        } else {
            int r2 = t >> 2, q2 = t & 3;
#pragma unroll
            for (int j = 0; j < 16; j++) {
                H1H[r2 * 68 + q2 * 16 + j] = 0u;
                H1L[r2 * 68 + q2 * 16 + j] = 0u;
            }
        }
    }
    __syncthreads();

    const int n0 = w * 16;
    const int lrow = (lane & 7) + ((lane >> 3 & 1) << 3);
    const int lkw  = (lane >> 4) << 2;
    unsigned baseH[4], baseL[4];
#pragma unroll
    for (int mt = 0; mt < 4; mt++) {
        baseH[mt] = smem_u32(&H1H[(mt * 16 + lrow) * 68 + lkw]);
        baseL[mt] = smem_u32(&H1L[(mt * 16 + lrow) * 68 + lkw]);
    }

    float acc[4][2][4];
#pragma unroll
    for (int a = 0; a < 4; a++)
#pragma unroll
        for (int b = 0; b < 2; b++)
#pragma unroll
            for (int c = 0; c < 4; c++) acc[a][b][c] = 0.f;

    for (int ks = 0; ks < 8; ks++) {
        unsigned ah[4][4], al[4][4];
#pragma unroll
        for (int mt = 0; mt < 4; mt++) {
            ldsm_x4(ah[mt], baseH[mt] + ks * 32);
            ldsm_x4(al[mt], baseL[mt] + ks * 32);
        }
#pragma unroll
        for (int nt = 0; nt < 2; nt++) {
            uint4 b = __ldg(&g_wAp[(ks * 4 + q4) * D_MODEL + n0 + nt * 8 + g4]);
#pragma unroll
            for (int mt = 0; mt < 4; mt++) mma16816(acc[mt][nt], ah[mt], b.x, b.y);
#pragma unroll
            for (int mt = 0; mt < 4; mt++) mma16816(acc[mt][nt], ah[mt], b.z, b.w);
#pragma unroll
            for (int mt = 0; mt < 4; mt++) mma16816(acc[mt][nt], al[mt], b.x, b.y);
        }
    }
    __syncthreads();

#pragma unroll
    for (int nt = 0; nt < 2; nt++) {
        int c = n0 + nt * 8 + q4 * 2;
#pragma unroll
        for (int mt = 0; mt < 4; mt++) {
            int r1 = mt * 16 + g4, r2 = r1 + 8;
            XS[r1 * 132 + c]     = acc[mt][nt][0];
            XS[r1 * 132 + c + 1] = acc[mt][nt][1];
            XS[r2 * 132 + c]     = acc[mt][nt][2];
            XS[r2 * 132 + c + 1] = acc[mt][nt][3];
        }
    }
    __syncthreads();

    for (int idx = t; idx < 64 * 32; idx += 256) {
        int row = idx >> 5, c4 = idx & 31;
        if (row < valid)
            *(float4*)(g_x + (size_t)(row0 + row) * D_MODEL + c4 * 4) =
                *(float4*)&XS[row * 132 + c4 * 4];
    }

    {
        int row = w * 8 + (lane >> 2);
        int h0 = q4 * 2;
        if (row < valid) {
            float ps0 = 0.f, pd0 = 0.f, ps1 = 0.f, pd1 = 0.f;
#pragma unroll
            for (int j = 0; j < 16; j++) {
                float x0 = XS[row * 132 + h0 * 16 + j];
                float x1 = XS[row * 132 + (h0 + 1) * 16 + j];
                ps0 += x0 * __ldg(asrc + h0 * DH + j);
                pd0 += x0 * __ldg(adst + h0 * DH + j);
                ps1 += x1 * __ldg(asrc + (h0 + 1) * DH + j);
                pd1 += x1 * __ldg(adst + (h0 + 1) * DH + j);
            }
            int grow = row0 + row;
            g_as[grow * 8 + h0] = ps0;     g_ad[grow * 8 + h0] = pd0;
            g_as[grow * 8 + h0 + 1] = ps1; g_ad[grow * 8 + h0 + 1] = pd1;
        }
    }
}

// ---------------- K45: fused gather + LN2 + FFN + residual -----------
// 64 rows/block, 256 threads, 2 CTAs/SM. Phase G: warp w gathers
// attention for rows w*8..w*8+7 (RMW out). Then the R13 k5 pipeline.
#define S5_H2H  0
#define S5_H2L  4352
#define S5_ACTH 8704
#define S5_ACTL 17152
#define S5_TOT  25600   // words -> 102,400 bytes

__global__ void __launch_bounds__(256, 2) k45_gather_ffn(float* __restrict__ out,
                                                         const float* __restrict__ g2,
                                                         const float* __restrict__ b2v,
                                                         const float* __restrict__ bb1,
                                                         const float* __restrict__ bb2) {
    extern __shared__ unsigned sm[];
    unsigned* H2H = sm + S5_H2H;
    unsigned* H2L = sm + S5_H2L;
    unsigned* ACTH = sm + S5_ACTH;
    unsigned* ACTL = sm + S5_ACTL;

    const int t = threadIdx.x;
    const int lane = t & 31, w = t >> 5;
    const int g4 = lane >> 2, q4 = lane & 3;
    const int row0 = blockIdx.x * 64;
    const int valid = min(64, N_NODES - row0);

    const int lrow = (lane & 7) + ((lane >> 3 & 1) << 3);
    const int lkw  = (lane >> 4) << 2;

    // ---- Phase G: attention gather, warp w -> rows w*8..w*8+7 ----
    {
        const int hc = lane >> 2;
#pragma unroll 1
        for (int i = 0; i < 8; i++) {
            const int dst = row0 + w * 8 + i;
            if (dst >= N_NODES) break;
            const int start = g_off[dst], end = g_off[dst + 1];

            const float adv = __ldg(&g_ad[dst * 8 + hc]);
            const float es_self = expf(leaky(__ldg(&g_as[dst * 8 + hc]) + adv));

            float4 xd = *(const float4*)(g_x + (size_t)dst * D_MODEL + lane * 4);
            float den = es_self;
            float4 acc = make_float4(es_self * xd.x, es_self * xd.y,
                                     es_self * xd.z, es_self * xd.w);

            int e = start;
            for (; e + 1 < end; e += 2) {
                int s0 = __ldg(&g_srcs[e]), s1 = __ldg(&g_srcs[e + 1]);
                float l0 = __ldg(&g_as[s0 * 8 + hc]), l1 = __ldg(&g_as[s1 * 8 + hc]);
                float4 x0 = *(const float4*)(g_x + (size_t)s0 * D_MODEL + lane * 4);
                float4 x1 = *(const float4*)(g_x + (size_t)s1 * D_MODEL + lane * 4);
                float a0 = expf(leaky(l0 + adv)), a1 = expf(leaky(l1 + adv));
                den += a0 + a1;
                acc.x += a0 * x0.x + a1 * x1.x;
                acc.y += a0 * x0.y + a1 * x1.y;
                acc.z += a0 * x0.z + a1 * x1.z;
                acc.w += a0 * x0.w + a1 * x1.w;
            }
            if (e < end) {
                int s0 = __ldg(&g_srcs[e]);
                float a0 = expf(leaky(__ldg(&g_as[s0 * 8 + hc]) + adv));
                float4 x0 = *(const float4*)(g_x + (size_t)s0 * D_MODEL + lane * 4);
                den += a0;
                acc.x += a0 * x0.x; acc.y += a0 * x0.y;
                acc.z += a0 * x0.z; acc.w += a0 * x0.w;
            }
            const float r = 1.f / (den + 1e-16f);
            float4* p = (float4*)(out + (size_t)dst * D_MODEL + lane * 4);
            float4 o = *p;
            o.x += acc.x * r; o.y += acc.y * r; o.z += acc.z * r; o.w += acc.w * r;
            *p = o;
        }
    }
    __syncthreads();

    // ---- Phase A: LN2 (reads the rows this block just updated) ----
    {
        int r = t >> 2, q = t & 3;
        if (r < valid) {
            int grow = row0 + r;
            const float4* rp = (const float4*)(out + (size_t)grow * D_MODEL + q * 32);
            float v[32];
#pragma unroll
            for (int j = 0; j < 8; j++) {
                float4 x = rp[j];
                v[4 * j] = x.x; v[4 * j + 1] = x.y; v[4 * j + 2] = x.z; v[4 * j + 3] = x.w;
            }
            float s = 0.f, s2 = 0.f;
#pragma unroll
            for (int j = 0; j < 32; j++) { s += v[j]; s2 += v[j] * v[j]; }
            s  += __shfl_xor_sync(0xffffffffu, s, 1);
            s  += __shfl_xor_sync(0xffffffffu, s, 2);
            s2 += __shfl_xor_sync(0xffffffffu, s2, 1);
            s2 += __shfl_xor_sync(0xffffffffu, s2, 2);
            float mean = s * (1.f / 128.f);
            float var = (s2 * (1.f / 128.f) - mean * mean) * (128.f / 127.f);
            float rstd = 1.f / (sqrtf(fmaxf(var, 0.f)) + LN_EPS);
#pragma unroll
            for (int j = 0; j < 16; j++) {
                int c = q * 32 + 2 * j;
                float y0 = __ldg(g2 + c)     * (v[2 * j]     - mean) * rstd + __ldg(b2v + c);
                float y1 = __ldg(g2 + c + 1) * (v[2 * j + 1] - mean) * rstd + __ldg(b2v + c + 1);
                unsigned hi, lo;
                split_pack(y0, y1, hi, lo);
                H2H[r * 68 + q * 16 + j] = hi;
                H2L[r * 68 + q * 16 + j] = lo;
            }
        } else {
#pragma unroll
            for (int j = 0; j < 16; j++) {
                H2H[r * 68 + q * 16 + j] = 0u;
                H2L[r * 68 + q * 16 + j] = 0u;
            }
        }
    }
    __syncthreads();

    unsigned bH2H[4], bH2L[4], bAH[4], bAL[4];
#pragma unroll
    for (int mt = 0; mt < 4; mt++) {
        bH2H[mt] = smem_u32(&H2H[(mt * 16 + lrow) * 68 + lkw]);
        bH2L[mt] = smem_u32(&H2L[(mt * 16 + lrow) * 68 + lkw]);
        bAH[mt]  = smem_u32(&ACTH[(mt * 16 + lrow) * 132 + lkw]);
        bAL[mt]  = smem_u32(&ACTL[(mt * 16 + lrow) * 132 + lkw]);
    }

    float acc2[4][2][4];
#pragma unroll
    for (int a = 0; a < 4; a++)
#pragma unroll
        for (int b = 0; b < 2; b++)
#pragma unroll
            for (int c = 0; c < 4; c++) acc2[a][b][c] = 0.f;

    for (int ch = 0; ch < 2; ch++) {
        {
            const int n0g = ch * 256 + w * 32;
            float acc1[4][4][4];
#pragma unroll
            for (int a = 0; a < 4; a++)
#pragma unroll
                for (int b = 0; b < 4; b++)
#pragma unroll
                    for (int c = 0; c < 4; c++) acc1[a][b][c] = 0.f;

            for (int ks = 0; ks < 8; ks++) {
                unsigned ah[4][4], al[4][4];
#pragma unroll
                for (int mt = 0; mt < 4; mt++) {
                    ldsm_x4(ah[mt], bH2H[mt] + ks * 32);
                    ldsm_x4(al[mt], bH2L[mt] + ks * 32);
                }
#pragma unroll
                for (int nt = 0; nt < 4; nt++) {
                    uint4 b = __ldg(&g_w1p[(ks * 4 + q4) * DFF + n0g + nt * 8 + g4]);
#pragma unroll
                    for (int mt = 0; mt < 4; mt++) mma16816(acc1[mt][nt], ah[mt], b.x, b.y);
#pragma unroll
                    for (int mt = 0; mt < 4; mt++) mma16816(acc1[mt][nt], ah[mt], b.z, b.w);
#pragma unroll
                    for (int mt = 0; mt < 4; mt++) mma16816(acc1[mt][nt], al[mt], b.x, b.y);
                }
            }
#pragma unroll
            for (int nt = 0; nt < 4; nt++) {
                int cg = n0g + nt * 8 + q4 * 2;
                float bi0 = __ldg(bb1 + cg), bi1 = __ldg(bb1 + cg + 1);
                int cp = w * 16 + nt * 4 + q4;
#pragma unroll
                for (int mt = 0; mt < 4; mt++) {
                    int r1 = mt * 16 + g4, r2 = r1 + 8;
                    unsigned hi, lo;
                    split_pack(fmaxf(acc1[mt][nt][0] + bi0, 0.f),
                               fmaxf(acc1[mt][nt][1] + bi1, 0.f), hi, lo);
                    ACTH[r1 * 132 + cp] = hi; ACTL[r1 * 132 + cp] = lo;
                    split_pack(fmaxf(acc1[mt][nt][2] + bi0, 0.f),
                               fmaxf(acc1[mt][nt][3] + bi1, 0.f), hi, lo);
                    ACTH[r2 * 132 + cp] = hi; ACTL[r2 * 132 + cp] = lo;
                }
            }
        }
        __syncthreads();

        {
            const int n0 = w * 16;
            for (int ksl = 0; ksl < 16; ksl++) {
                unsigned ah[4][4], al[4][4];
#pragma unroll
                for (int mt = 0; mt < 4; mt++) {
                    ldsm_x4(ah[mt], bAH[mt] + ksl * 32);
                    ldsm_x4(al[mt], bAL[mt] + ksl * 32);
                }
                int ksg = ch * 16 + ksl;
#pragma unroll
                for (int nt = 0; nt < 2; nt++) {
                    uint4 b = __ldg(&g_w2p[(ksg * 4 + q4) * D_MODEL + n0 + nt * 8 + g4]);
#pragma unroll
                    for (int mt = 0; mt < 4; mt++) mma16816(acc2[mt][nt], ah[mt], b.x, b.y);
#pragma unroll
                    for (int mt = 0; mt < 4; mt++) mma16816(acc2[mt][nt], ah[mt], b.z, b.w);
#pragma unroll
                    for (int mt = 0; mt < 4; mt++) mma16816(acc2[mt][nt], al[mt], b.x, b.y);
                }
            }
        }
        __syncthreads();
    }

    {
        const int n0 = w * 16;
#pragma unroll
        for (int nt = 0; nt < 2; nt++) {
            int c = n0 + nt * 8 + q4 * 2;
            float bi0 = __ldg(bb2 + c), bi1 = __ldg(bb2 + c + 1);
#pragma unroll
            for (int mt = 0; mt < 4; mt++) {
                int lr1 = mt * 16 + g4, lr2 = lr1 + 8;
                if (lr1 < valid) {
                    float* p = out + (size_t)(row0 + lr1) * D_MODEL + c;
                    float2 o = *(float2*)p;
                    o.x += acc2[mt][nt][0] + bi0;
                    o.y += acc2[mt][nt][1] + bi1;
                    *(float2*)p = o;
                }
                if (lr2 < valid) {
                    float* p = out + (size_t)(row0 + lr2) * D_MODEL + c;
                    float2 o = *(float2*)p;
                    o.x += acc2[mt][nt][2] + bi0;
                    o.y += acc2[mt][nt][3] + bi1;
                    *(float2*)p = o;
                }
            }
        }
    }
}

// ---------------- host launcher -----------------------------------
extern "C" void kernel_launch(void* const* d_in, const int* in_sizes, int n_in,
                              void* d_out, int out_size) {
    const float* nf       = (const float*)d_in[0];
    const int*   ei       = (const int*)d_in[1];     // JAX demotes int64 -> int32
    const float* ln1_g    = (const float*)d_in[2];
    const float* ln1_b    = (const float*)d_in[3];
    const float* W_att    = (const float*)d_in[4];
    const float* att_src  = (const float*)d_in[5];
    const float* att_dst  = (const float*)d_in[6];
    const float* bias_att = (const float*)d_in[7];
    const float* ln2_g    = (const float*)d_in[8];
    const float* ln2_b    = (const float*)d_in[9];
    const float* W1       = (const float*)d_in[10];
    const float* b1       = (const float*)d_in[11];
    const float* W2       = (const float*)d_in[12];
    const float* b2       = (const float*)d_in[13];
    float* out = (float*)d_out;

    static cudaStream_t s2 = nullptr;
    static cudaEvent_t ev_fork = nullptr, ev_join = nullptr;
    if (!s2) {
        cudaFuncSetAttribute(k45_gather_ffn, cudaFuncAttributeMaxDynamicSharedMemorySize,
                             S5_TOT * 4);
        cudaStreamCreateWithFlags(&s2, cudaStreamNonBlocking);
        cudaEventCreateWithFlags(&ev_fork, cudaEventDisableTiming);
        cudaEventCreateWithFlags(&ev_join, cudaEventDisableTiming);
    }

    const int egrid = (E_EDGES + 255) / 256;

    // prep: weight split/pack + histogram zero (one grid, main stream)
    kprep<<<PREP_B + SCAN_B, 256>>>(W1, W2, W_att);

    // fork: CSR chain on s2, concurrent with k1 on main stream
    cudaEventRecord(ev_fork, 0);
    cudaStreamWaitEvent(s2, ev_fork, 0);
    ks_hist<<<egrid, 256, 0, s2>>>(ei);
    ks_scan1<<<SCAN_B, 256, 0, s2>>>();
    ks_scan3<<<SCAN_B, 256, 0, s2>>>();
    ks_scat<<<egrid, 256, 0, s2>>>(ei);
    cudaEventRecord(ev_join, s2);

    // main stream: K1
    k1_ln_proj<<<K1_B, 256, 8704 * 4>>>(nf, ln1_g, ln1_b, bias_att,
                                        att_src, att_dst, out);

    // join, then fused gather + FFN
    cudaStreamWaitEvent(0, ev_join, 0);
    k45_gather_ffn<<<K1_B, 256, S5_TOT * 4>>>(out, ln2_g, ln2_b, b1, b2);
}

// round 17
// speedup vs baseline: 1.1980x; 1.1980x over previous
#include <cuda_runtime.h>
#include <cuda_bf16.h>
#include <math.h>

#define N_NODES 50000
#define D_MODEL 128
#define H_HEADS 8
#define DH 16
#define DFF 512
#define E_EDGES 800000
#define LN_EPS 1e-6f
#define NEG_SLOPE 0.2f
#define SCAN_B 196           // 196*256 = 50176 >= N_NODES+1
#define PREP_B 144           // kprep weight blocks
#define K1_B   782           // blocks: ceil(50000/64)

// ---------------- scratch (no allocations allowed) ----------------
__device__ __align__(16) float g_x[(size_t)N_NODES * D_MODEL];   // projected features [N,128]
__device__ __align__(16) float g_as[N_NODES * H_HEADS];          // alpha_src logits
__device__ __align__(16) float g_ad[N_NODES * H_HEADS];          // alpha_dst logits
// CSR-by-dst build
__device__ __align__(16) unsigned g_cnt[SCAN_B * 256];
__device__ __align__(16) unsigned g_off[N_NODES + 1];
__device__ __align__(16) unsigned g_cur[N_NODES];
__device__ __align__(16) unsigned g_bsum[256];
__device__ __align__(16) int      g_srcs[E_EDGES];
// packed split-bf16 weights: uint4 = (hi[kh], hi[kh+4], lo[kh], lo[kh+4])
__device__ __align__(16) uint4 g_w1p[32 * DFF];                  // W1 (k=128 -> 32 khIdx)
__device__ __align__(16) uint4 g_w2p[128 * D_MODEL];             // W2 (k=512 -> 128 khIdx)
__device__ __align__(16) uint4 g_wAp[32 * D_MODEL];              // W_att

__device__ __forceinline__ float leaky(float x) { return x > 0.f ? x : NEG_SLOPE * x; }

__device__ __forceinline__ void split_pack(float x0, float x1, unsigned& hi, unsigned& lo) {
    __nv_bfloat162 h = __floats2bfloat162_rn(x0, x1);
    float2 hf = __bfloat1622float2(h);
    __nv_bfloat162 l = __floats2bfloat162_rn(x0 - hf.x, x1 - hf.y);
    hi = *reinterpret_cast<unsigned*>(&h);
    lo = *reinterpret_cast<unsigned*>(&l);
}

__device__ __forceinline__ void mma16816(float* c, const unsigned* a, unsigned b0, unsigned b1) {
    asm volatile(
        "mma.sync.aligned.m16n8k16.row.col.f32.bf16.bf16.f32 "
        "{%0,%1,%2,%3}, {%4,%5,%6,%7}, {%8,%9}, {%0,%1,%2,%3};"
        : "+f"(c[0]), "+f"(c[1]), "+f"(c[2]), "+f"(c[3])
        : "r"(a[0]), "r"(a[1]), "r"(a[2]), "r"(a[3]), "r"(b0), "r"(b1));
}

__device__ __forceinline__ void ldsm_x4(unsigned* r, unsigned addr) {
    asm volatile("ldmatrix.sync.aligned.m8n8.x4.shared.b16 {%0,%1,%2,%3}, [%4];"
        : "=r"(r[0]), "=r"(r[1]), "=r"(r[2]), "=r"(r[3]) : "r"(addr));
}

__device__ __forceinline__ unsigned smem_u32(const void* p) {
    return (unsigned)__cvta_generic_to_shared(p);
}

// ---------------- Kprep: weight split/pack + g_cnt zero (fused) ----
__global__ void __launch_bounds__(256) kprep(const float* __restrict__ W1,
                                             const float* __restrict__ W2,
                                             const float* __restrict__ WA) {
    if (blockIdx.x >= PREP_B) {              // zero g_cnt
        g_cnt[(blockIdx.x - PREP_B) * 256 + threadIdx.x] = 0u;
        return;
    }
    int i = blockIdx.x * 256 + threadIdx.x;
    const float* W; int cols, idx; uint4* dst;
    if (i < 32 * DFF)                       { W = W1; cols = DFF;     idx = i;                       dst = g_w1p; }
    else if (i < 32 * DFF + 128 * D_MODEL)  { W = W2; cols = D_MODEL; idx = i - 32 * DFF;            dst = g_w2p; }
    else                                    { W = WA; cols = D_MODEL; idx = i - 32 * DFF - 128 * D_MODEL; dst = g_wAp; }
    int khi = idx / cols, n = idx % cols;
    int ks = khi >> 2, q = khi & 3;
    int kh = ks * 8 + q;
    unsigned h0, l0, h1, l1;
    split_pack(W[(2 * kh) * cols + n],     W[(2 * kh + 1) * cols + n], h0, l0);
    split_pack(W[(2 * kh + 8) * cols + n], W[(2 * kh + 9) * cols + n], h1, l1);
    dst[idx] = make_uint4(h0, h1, l0, l1);
}

// ---------------- CSR build -----------------------------------------
__global__ void __launch_bounds__(256) ks_hist(const int* __restrict__ ei) {
    int e = blockIdx.x * 256 + threadIdx.x;
    if (e < E_EDGES) atomicAdd(&g_cnt[__ldg(ei + E_EDGES + e)], 1u);
}
__global__ void __launch_bounds__(256) ks_scan1() {
    __shared__ unsigned s[256];
    int t = threadIdx.x;
    s[t] = g_cnt[blockIdx.x * 256 + t];
    __syncthreads();
#pragma unroll
    for (int o = 128; o; o >>= 1) {
        if (t < o) s[t] += s[t + o];
        __syncthreads();
    }
    if (t == 0) g_bsum[blockIdx.x] = s[0];
}
__global__ void __launch_bounds__(256) ks_scan3() {
    __shared__ unsigned s[256];
    __shared__ unsigned boff_s;
    int t = threadIdx.x;
    {
        unsigned v = (t < blockIdx.x && t < SCAN_B) ? g_bsum[t] : 0u;
        s[t] = v;
        __syncthreads();
#pragma unroll
        for (int o = 128; o; o >>= 1) {
            if (t < o) s[t] += s[t + o];
            __syncthreads();
        }
        if (t == 0) boff_s = s[0];
        __syncthreads();
    }
    int i = blockIdx.x * 256 + t;
    unsigned v = g_cnt[i];
    s[t] = v;
    __syncthreads();
#pragma unroll
    for (int o = 1; o < 256; o <<= 1) {
        unsigned add = (t >= o) ? s[t - o] : 0u;
        __syncthreads();
        s[t] += add;
        __syncthreads();
    }
    unsigned excl = s[t] - v + boff_s;
    if (i <= N_NODES) g_off[i] = excl;
    if (i < N_NODES)  g_cur[i] = excl;
}
__global__ void __launch_bounds__(256) ks_scat(const int* __restrict__ ei) {
    int e = blockIdx.x * 256 + threadIdx.x;
    if (e >= E_EDGES) return;
    int src = __ldg(ei + e), dst = __ldg(ei + E_EDGES + e);
    unsigned p = atomicAdd(&g_cur[dst], 1u);
    g_srcs[p] = src;
}

// ---------------- K1: LN1 -> x = h1 @ W_att (MMA); a_s, a_d; out=nf+bias
__global__ void __launch_bounds__(256) k1_ln_proj(const float* __restrict__ nf,
                                                  const float* __restrict__ g1,
                                                  const float* __restrict__ b1v,
                                                  const float* __restrict__ bias_att,
                                                  const float* __restrict__ asrc,
                                                  const float* __restrict__ adst,
                                                  float* __restrict__ out) {
    extern __shared__ unsigned sm[];
    unsigned* H1H = sm;
    unsigned* H1L = sm + 4352;
    float* XS = (float*)sm;              // aliases H1 after phase B

    const int t = threadIdx.x;
    const int lane = t & 31, w = t >> 5;
    const int g4 = lane >> 2, q4 = lane & 3;
    const int row0 = blockIdx.x * 64;
    const int valid = min(64, N_NODES - row0);

    {
        int r = t >> 2, q = t & 3;
        if (r < valid) {
            int grow = row0 + r;
            const float4* rp = (const float4*)(nf + (size_t)grow * D_MODEL + q * 32);
            float v[32];
#pragma unroll
            for (int j = 0; j < 8; j++) {
                float4 x = rp[j];
                v[4 * j] = x.x; v[4 * j + 1] = x.y; v[4 * j + 2] = x.z; v[4 * j + 3] = x.w;
            }
            float4* op = (float4*)(out + (size_t)grow * D_MODEL + q * 32);
#pragma unroll
            for (int j = 0; j < 8; j++) {
                int c = q * 32 + 4 * j;
                op[j] = make_float4(v[4 * j]     + __ldg(bias_att + c),
                                    v[4 * j + 1] + __ldg(bias_att + c + 1),
                                    v[4 * j + 2] + __ldg(bias_att + c + 2),
                                    v[4 * j + 3] + __ldg(bias_att + c + 3));
            }
            float s = 0.f, s2 = 0.f;
#pragma unroll
            for (int j = 0; j < 32; j++) { s += v[j]; s2 += v[j] * v[j]; }
            s  += __shfl_xor_sync(0xffffffffu, s, 1);
            s  += __shfl_xor_sync(0xffffffffu, s, 2);
            s2 += __shfl_xor_sync(0xffffffffu, s2, 1);
            s2 += __shfl_xor_sync(0xffffffffu, s2, 2);
            float mean = s * (1.f / 128.f);
            float var = (s2 * (1.f / 128.f) - mean * mean) * (128.f / 127.f);
            float rstd = 1.f / (sqrtf(fmaxf(var, 0.f)) + LN_EPS);
#pragma unroll
            for (int j = 0; j < 16; j++) {
                int c = q * 32 + 2 * j;
                float y0 = __ldg(g1 + c)     * (v[2 * j]     - mean) * rstd + __ldg(b1v + c);
                float y1 = __ldg(g1 + c + 1) * (v[2 * j + 1] - mean) * rstd + __ldg(b1v + c + 1);
                unsigned hi, lo;
                split_pack(y0, y1, hi, lo);
                H1H[r * 68 + q * 16 + j] = hi;
                H1L[r * 68 + q * 16 + j] = lo;
            }
        } else {
            int r2 = t >> 2, q2 = t & 3;
#pragma unroll
            for (int j = 0; j < 16; j++) {
                H1H[r2 * 68 + q2 * 16 + j] = 0u;
                H1L[r2 * 68 + q2 * 16 + j] = 0u;
            }
        }
    }
    __syncthreads();

    const int n0 = w * 16;
    const int lrow = (lane & 7) + ((lane >> 3 & 1) << 3);
    const int lkw  = (lane >> 4) << 2;
    unsigned baseH[4], baseL[4];
#pragma unroll
    for (int mt = 0; mt < 4; mt++) {
        baseH[mt] = smem_u32(&H1H[(mt * 16 + lrow) * 68 + lkw]);
        baseL[mt] = smem_u32(&H1L[(mt * 16 + lrow) * 68 + lkw]);
    }

    float acc[4][2][4];
#pragma unroll
    for (int a = 0; a < 4; a++)
#pragma unroll
        for (int b = 0; b < 2; b++)
#pragma unroll
            for (int c = 0; c < 4; c++) acc[a][b][c] = 0.f;

    for (int ks = 0; ks < 8; ks++) {
        unsigned ah[4][4], al[4][4];
#pragma unroll
        for (int mt = 0; mt < 4; mt++) {
            ldsm_x4(ah[mt], baseH[mt] + ks * 32);
            ldsm_x4(al[mt], baseL[mt] + ks * 32);
        }
#pragma unroll
        for (int nt = 0; nt < 2; nt++) {
            uint4 b = __ldg(&g_wAp[(ks * 4 + q4) * D_MODEL + n0 + nt * 8 + g4]);
#pragma unroll
            for (int mt = 0; mt < 4; mt++) mma16816(acc[mt][nt], ah[mt], b.x, b.y);
#pragma unroll
            for (int mt = 0; mt < 4; mt++) mma16816(acc[mt][nt], ah[mt], b.z, b.w);
#pragma unroll
            for (int mt = 0; mt < 4; mt++) mma16816(acc[mt][nt], al[mt], b.x, b.y);
        }
    }
    __syncthreads();

#pragma unroll
    for (int nt = 0; nt < 2; nt++) {
        int c = n0 + nt * 8 + q4 * 2;
#pragma unroll
        for (int mt = 0; mt < 4; mt++) {
            int r1 = mt * 16 + g4, r2 = r1 + 8;
            XS[r1 * 132 + c]     = acc[mt][nt][0];
            XS[r1 * 132 + c + 1] = acc[mt][nt][1];
            XS[r2 * 132 + c]     = acc[mt][nt][2];
            XS[r2 * 132 + c + 1] = acc[mt][nt][3];
        }
    }
    __syncthreads();

    for (int idx = t; idx < 64 * 32; idx += 256) {
        int row = idx >> 5, c4 = idx & 31;
        if (row < valid)
            *(float4*)(g_x + (size_t)(row0 + row) * D_MODEL + c4 * 4) =
                *(float4*)&XS[row * 132 + c4 * 4];
    }

    {
        int row = w * 8 + (lane >> 2);
        int h0 = q4 * 2;
        if (row < valid) {
            float ps0 = 0.f, pd0 = 0.f, ps1 = 0.f, pd1 = 0.f;
#pragma unroll
            for (int j = 0; j < 16; j++) {
                float x0 = XS[row * 132 + h0 * 16 + j];
                float x1 = XS[row * 132 + (h0 + 1) * 16 + j];
                ps0 += x0 * __ldg(asrc + h0 * DH + j);
                pd0 += x0 * __ldg(adst + h0 * DH + j);
                ps1 += x1 * __ldg(asrc + (h0 + 1) * DH + j);
                pd1 += x1 * __ldg(adst + (h0 + 1) * DH + j);
            }
            int grow = row0 + row;
            g_as[grow * 8 + h0] = ps0;     g_ad[grow * 8 + h0] = pd0;
            g_as[grow * 8 + h0 + 1] = ps1; g_ad[grow * 8 + h0 + 1] = pd1;
        }
    }
}

// ---------------- K4: single-pass gather (warp per dst, 2-way ILP) --
__global__ void __launch_bounds__(256) k4_gather(float* __restrict__ out) {
    int wid = (blockIdx.x * 256 + threadIdx.x) >> 5;
    int lane = threadIdx.x & 31;
    if (wid >= N_NODES) return;
    const int dst = wid;
    const int start = g_off[dst], end = g_off[dst + 1];
    const int hc = lane >> 2;

    const float adv = __ldg(&g_ad[dst * 8 + hc]);
    const float es_self = expf(leaky(__ldg(&g_as[dst * 8 + hc]) + adv));

    // prefetch residual row early so the final RMW has no dependent-load tail
    float4* p = (float4*)(out + (size_t)dst * D_MODEL + lane * 4);
    float4 o = *p;

    float4 xd = *(const float4*)(g_x + (size_t)dst * D_MODEL + lane * 4);
    float den = es_self;
    float4 acc = make_float4(es_self * xd.x, es_self * xd.y, es_self * xd.z, es_self * xd.w);

    int e = start;
    for (; e + 1 < end; e += 2) {
        int s0 = __ldg(&g_srcs[e]), s1 = __ldg(&g_srcs[e + 1]);
        float l0 = __ldg(&g_as[s0 * 8 + hc]), l1 = __ldg(&g_as[s1 * 8 + hc]);
        float4 x0 = *(const float4*)(g_x + (size_t)s0 * D_MODEL + lane * 4);
        float4 x1 = *(const float4*)(g_x + (size_t)s1 * D_MODEL + lane * 4);
        float a0 = expf(leaky(l0 + adv)), a1 = expf(leaky(l1 + adv));
        den += a0 + a1;
        acc.x += a0 * x0.x + a1 * x1.x;
        acc.y += a0 * x0.y + a1 * x1.y;
        acc.z += a0 * x0.z + a1 * x1.z;
        acc.w += a0 * x0.w + a1 * x1.w;
    }
    if (e < end) {
        int s0 = __ldg(&g_srcs[e]);
        float a0 = expf(leaky(__ldg(&g_as[s0 * 8 + hc]) + adv));
        float4 x0 = *(const float4*)(g_x + (size_t)s0 * D_MODEL + lane * 4);
        den += a0;
        acc.x += a0 * x0.x; acc.y += a0 * x0.y; acc.z += a0 * x0.z; acc.w += a0 * x0.w;
    }
    const float r = 1.f / (den + 1e-16f);
    o.x += acc.x * r; o.y += acc.y * r; o.z += acc.z * r; o.w += acc.w * r;
    *p = o;
}

// ---------------- K5: fused LN2 + FFN + residual (chunked ACT) -------
#define S5_H2H  0
#define S5_H2L  4352
#define S5_ACTH 8704
#define S5_ACTL 17152
#define S5_TOT  25600   // words -> 102,400 bytes

__global__ void __launch_bounds__(256, 2) k5_ffn(float* __restrict__ out,
                                                 const float* __restrict__ g2,
                                                 const float* __restrict__ b2v,
                                                 const float* __restrict__ bb1,
                                                 const float* __restrict__ bb2) {
    extern __shared__ unsigned sm[];
    unsigned* H2H = sm + S5_H2H;
    unsigned* H2L = sm + S5_H2L;
    unsigned* ACTH = sm + S5_ACTH;
    unsigned* ACTL = sm + S5_ACTL;

    const int t = threadIdx.x;
    const int lane = t & 31, w = t >> 5;
    const int g4 = lane >> 2, q4 = lane & 3;
    const int row0 = blockIdx.x * 64;
    const int valid = min(64, N_NODES - row0);

    const int lrow = (lane & 7) + ((lane >> 3 & 1) << 3);
    const int lkw  = (lane >> 4) << 2;

    // ---- Phase A: LN2 ----
    {
        int r = t >> 2, q = t & 3;
        if (r < valid) {
            int grow = row0 + r;
            const float4* rp = (const float4*)(out + (size_t)grow * D_MODEL + q * 32);
            float v[32];
#pragma unroll
            for (int j = 0; j < 8; j++) {
                float4 x = rp[j];
                v[4 * j] = x.x; v[4 * j + 1] = x.y; v[4 * j + 2] = x.z; v[4 * j + 3] = x.w;
            }
            float s = 0.f, s2 = 0.f;
#pragma unroll
            for (int j = 0; j < 32; j++) { s += v[j]; s2 += v[j] * v[j]; }
            s  += __shfl_xor_sync(0xffffffffu, s, 1);
            s  += __shfl_xor_sync(0xffffffffu, s, 2);
            s2 += __shfl_xor_sync(0xffffffffu, s2, 1);
            s2 += __shfl_xor_sync(0xffffffffu, s2, 2);
            float mean = s * (1.f / 128.f);
            float var = (s2 * (1.f / 128.f) - mean * mean) * (128.f / 127.f);
            float rstd = 1.f / (sqrtf(fmaxf(var, 0.f)) + LN_EPS);
#pragma unroll
            for (int j = 0; j < 16; j++) {
                int c = q * 32 + 2 * j;
                float y0 = __ldg(g2 + c)     * (v[2 * j]     - mean) * rstd + __ldg(b2v + c);
                float y1 = __ldg(g2 + c + 1) * (v[2 * j + 1] - mean) * rstd + __ldg(b2v + c + 1);
                unsigned hi, lo;
                split_pack(y0, y1, hi, lo);
                H2H[r * 68 + q * 16 + j] = hi;
                H2L[r * 68 + q * 16 + j] = lo;
            }
        } else {
#pragma unroll
            for (int j = 0; j < 16; j++) {
                H2H[r * 68 + q * 16 + j] = 0u;
                H2L[r * 68 + q * 16 + j] = 0u;
            }
        }
    }
    __syncthreads();

    unsigned bH2H[4], bH2L[4], bAH[4], bAL[4];
#pragma unroll
    for (int mt = 0; mt < 4; mt++) {
        bH2H[mt] = smem_u32(&H2H[(mt * 16 + lrow) * 68 + lkw]);
        bH2L[mt] = smem_u32(&H2L[(mt * 16 + lrow) * 68 + lkw]);
        bAH[mt]  = smem_u32(&ACTH[(mt * 16 + lrow) * 132 + lkw]);
        bAL[mt]  = smem_u32(&ACTL[(mt * 16 + lrow) * 132 + lkw]);
    }

    float acc2[4][2][4];
#pragma unroll
    for (int a = 0; a < 4; a++)
#pragma unroll
        for (int b = 0; b < 2; b++)
#pragma unroll
            for (int c = 0; c < 4; c++) acc2[a][b][c] = 0.f;

    for (int ch = 0; ch < 2; ch++) {
        {
            const int n0g = ch * 256 + w * 32;
            float acc1[4][4][4];
#pragma unroll
            for (int a = 0; a < 4; a++)
#pragma unroll
                for (int b = 0; b < 4; b++)
#pragma unroll
                    for (int c = 0; c < 4; c++) acc1[a][b][c] = 0.f;

            for (int ks = 0; ks < 8; ks++) {
                unsigned ah[4][4], al[4][4];
#pragma unroll
                for (int mt = 0; mt < 4; mt++) {
                    ldsm_x4(ah[mt], bH2H[mt] + ks * 32);
                    ldsm_x4(al[mt], bH2L[mt] + ks * 32);
                }
#pragma unroll
                for (int nt = 0; nt < 4; nt++) {
                    uint4 b = __ldg(&g_w1p[(ks * 4 + q4) * DFF + n0g + nt * 8 + g4]);
#pragma unroll
                    for (int mt = 0; mt < 4; mt++) mma16816(acc1[mt][nt], ah[mt], b.x, b.y);
#pragma unroll
                    for (int mt = 0; mt < 4; mt++) mma16816(acc1[mt][nt], ah[mt], b.z, b.w);
#pragma unroll
                    for (int mt = 0; mt < 4; mt++) mma16816(acc1[mt][nt], al[mt], b.x, b.y);
                }
            }
#pragma unroll
            for (int nt = 0; nt < 4; nt++) {
                int cg = n0g + nt * 8 + q4 * 2;
                float bi0 = __ldg(bb1 + cg), bi1 = __ldg(bb1 + cg + 1);
                int cp = w * 16 + nt * 4 + q4;
#pragma unroll
                for (int mt = 0; mt < 4; mt++) {
                    int r1 = mt * 16 + g4, r2 = r1 + 8;
                    unsigned hi, lo;
                    split_pack(fmaxf(acc1[mt][nt][0] + bi0, 0.f),
                               fmaxf(acc1[mt][nt][1] + bi1, 0.f), hi, lo);
                    ACTH[r1 * 132 + cp] = hi; ACTL[r1 * 132 + cp] = lo;
                    split_pack(fmaxf(acc1[mt][nt][2] + bi0, 0.f),
                               fmaxf(acc1[mt][nt][3] + bi1, 0.f), hi, lo);
                    ACTH[r2 * 132 + cp] = hi; ACTL[r2 * 132 + cp] = lo;
                }
            }
        }
        __syncthreads();

        {
            const int n0 = w * 16;
            for (int ksl = 0; ksl < 16; ksl++) {
                unsigned ah[4][4], al[4][4];
#pragma unroll
                for (int mt = 0; mt < 4; mt++) {
                    ldsm_x4(ah[mt], bAH[mt] + ksl * 32);
                    ldsm_x4(al[mt], bAL[mt] + ksl * 32);
                }
                int ksg = ch * 16 + ksl;
#pragma unroll
                for (int nt = 0; nt < 2; nt++) {
                    uint4 b = __ldg(&g_w2p[(ksg * 4 + q4) * D_MODEL + n0 + nt * 8 + g4]);
#pragma unroll
                    for (int mt = 0; mt < 4; mt++) mma16816(acc2[mt][nt], ah[mt], b.x, b.y);
#pragma unroll
                    for (int mt = 0; mt < 4; mt++) mma16816(acc2[mt][nt], ah[mt], b.z, b.w);
#pragma unroll
                    for (int mt = 0; mt < 4; mt++) mma16816(acc2[mt][nt], al[mt], b.x, b.y);
                }
            }
        }
        __syncthreads();
    }

    {
        const int n0 = w * 16;
#pragma unroll
        for (int nt = 0; nt < 2; nt++) {
            int c = n0 + nt * 8 + q4 * 2;
            float bi0 = __ldg(bb2 + c), bi1 = __ldg(bb2 + c + 1);
#pragma unroll
            for (int mt = 0; mt < 4; mt++) {
                int lr1 = mt * 16 + g4, lr2 = lr1 + 8;
                if (lr1 < valid) {
                    float* p = out + (size_t)(row0 + lr1) * D_MODEL + c;
                    float2 o = *(float2*)p;
                    o.x += acc2[mt][nt][0] + bi0;
                    o.y += acc2[mt][nt][1] + bi1;
                    *(float2*)p = o;
                }
                if (lr2 < valid) {
                    float* p = out + (size_t)(row0 + lr2) * D_MODEL + c;
                    float2 o = *(float2*)p;
                    o.x += acc2[mt][nt][2] + bi0;
                    o.y += acc2[mt][nt][3] + bi1;
                    *(float2*)p = o;
                }
            }
        }
    }
}

// ---------------- host launcher -----------------------------------
extern "C" void kernel_launch(void* const* d_in, const int* in_sizes, int n_in,
                              void* d_out, int out_size) {
    const float* nf       = (const float*)d_in[0];
    const int*   ei       = (const int*)d_in[1];     // JAX demotes int64 -> int32
    const float* ln1_g    = (const float*)d_in[2];
    const float* ln1_b    = (const float*)d_in[3];
    const float* W_att    = (const float*)d_in[4];
    const float* att_src  = (const float*)d_in[5];
    const float* att_dst  = (const float*)d_in[6];
    const float* bias_att = (const float*)d_in[7];
    const float* ln2_g    = (const float*)d_in[8];
    const float* ln2_b    = (const float*)d_in[9];
    const float* W1       = (const float*)d_in[10];
    const float* b1       = (const float*)d_in[11];
    const float* W2       = (const float*)d_in[12];
    const float* b2       = (const float*)d_in[13];
    float* out = (float*)d_out;

    static cudaStream_t s2 = nullptr;
    static cudaEvent_t ev_fork = nullptr, ev_join = nullptr;
    if (!s2) {
        cudaFuncSetAttribute(k5_ffn, cudaFuncAttributeMaxDynamicSharedMemorySize,
                             S5_TOT * 4);
        cudaStreamCreateWithFlags(&s2, cudaStreamNonBlocking);
        cudaEventCreateWithFlags(&ev_fork, cudaEventDisableTiming);
        cudaEventCreateWithFlags(&ev_join, cudaEventDisableTiming);
    }

    const int egrid = (E_EDGES + 255) / 256;

    // prep: weight split/pack + histogram zero (one grid, main stream)
    kprep<<<PREP_B + SCAN_B, 256>>>(W1, W2, W_att);

    // fork: CSR chain on s2, concurrent with k1 on main stream
    cudaEventRecord(ev_fork, 0);
    cudaStreamWaitEvent(s2, ev_fork, 0);
    ks_hist<<<egrid, 256, 0, s2>>>(ei);
    ks_scan1<<<SCAN_B, 256, 0, s2>>>();
    ks_scan3<<<SCAN_B, 256, 0, s2>>>();
    ks_scat<<<egrid, 256, 0, s2>>>(ei);
    cudaEventRecord(ev_join, s2);

    // main stream: K1
    k1_ln_proj<<<K1_B, 256, 8704 * 4>>>(nf, ln1_g, ln1_b, bias_att,
                                        att_src, att_dst, out);

    // join: k4 needs both k1 (logits, g_x, out) and CSR (g_off, g_srcs)
    cudaStreamWaitEvent(0, ev_join, 0);
    // K4: static warp-per-dst gather, 2-way ILP (R13 champion config)
    k4_gather<<<(N_NODES * 32 + 255) / 256, 256>>>(out);
    // K5: fused LN2 + FFN + residual, chunked ACT (2 CTAs/SM)
    k5_ffn<<<K1_B, 256, S5_TOT * 4>>>(out, ln2_g, ln2_b, b1, b2);
}